// round 10
// baseline (speedup 1.0000x reference)
#include <cuda_runtime.h>

// Sinkhorn-Knopp, 5 iterations, linear-domain scaling-vector formulation.
//
//   a_i = 1 / sum_j exp(A_ij) * b_j      (b init 1)
//   b_j = 1 / sum_i exp(A_ij) * a_i      (uses fresh a)
//   out = exp(A_ij) * a_i * b_j
//
// Mathematically identical to the reference's alternating log-space
// row/col logsumexp normalization (log_alpha == A - u_i - v_j with
// a = e^-u, b = e^-v). No max-subtraction needed: A ~ N(0,1), so all
// intermediate magnitudes are well inside fp32 range.
//
// Fused kernel: one DRAM sweep per iteration. Each CTA owns a 16-row
// tile of one 1024x1024 matrix, stages exp(A) in SMEM, computes its
// rows' a_i, then column partial sums over its 16 rows from SMEM.
// A combine kernel reduces the 64 tile-partials per column into b_j.

#define BATCH 64
#define N 1024
#define R 16                          // rows per tile
#define TILES_PER_MAT (N / R)         // 64
#define NTILES (BATCH * TILES_PER_MAT)// 4096
#define THREADS 512
#define ITERS 5

// Scratch (allocation-free: __device__ globals)
__device__ float g_a[BATCH * N];                 // 256 KB
__device__ float g_b[BATCH * N];                 // 256 KB
__device__ float g_part[(size_t)NTILES * N];     // 16 MB

__global__ __launch_bounds__(THREADS, 3)
void sinkhorn_fused_kernel(const float* __restrict__ A, int first)
{
    __shared__ float bs[N];        // current b for this matrix
    __shared__ float a_sm[R];      // fresh a for this tile's rows
    extern __shared__ float tile[];// R * N floats of exp(A), 64 KB

    const int tid  = threadIdx.x;
    const int m    = blockIdx.x / TILES_PER_MAT;
    const int t    = blockIdx.x % TILES_PER_MAT;
    const int row0 = t * R;

    // Preload b (1.0 on first iteration)
    if (first) {
        bs[tid]       = 1.0f;
        bs[tid + 512] = 1.0f;
    } else {
        bs[tid]       = g_b[m * N + tid];
        bs[tid + 512] = g_b[m * N + tid + 512];
    }
    __syncthreads();

    // ---- Phase A: warp w handles row (row0 + w). Compute
    //      r = sum_j exp(A_ij) * b_j, stage exp(A) in SMEM. ----
    const int w   = tid >> 5;      // 0..15
    const int l   = tid & 31;
    const int row = row0 + w;

    const float4* A4 =
        reinterpret_cast<const float4*>(A) + ((size_t)m * N + row) * (N / 4);
    float4*       tile4 = reinterpret_cast<float4*>(tile + w * N);
    const float4* bs4   = reinterpret_cast<const float4*>(bs);

    float acc = 0.0f;
    #pragma unroll
    for (int k = 0; k < 8; k++) {
        int c4 = k * 32 + l;               // float4 index within row
        float4 v = A4[c4];
        float4 e;
        e.x = __expf(v.x); e.y = __expf(v.y);
        e.z = __expf(v.z); e.w = __expf(v.w);
        tile4[c4] = e;
        float4 bb = bs4[c4];
        acc += e.x * bb.x + e.y * bb.y + e.z * bb.z + e.w * bb.w;
    }
    #pragma unroll
    for (int off = 16; off; off >>= 1)
        acc += __shfl_xor_sync(0xffffffffu, acc, off);
    if (l == 0) {
        float a = 1.0f / acc;
        a_sm[w] = a;
        g_a[m * N + row] = a;              // consumed by final kernel
    }
    __syncthreads();

    // ---- Phase B: column partials over this tile's 16 rows ----
    #pragma unroll
    for (int rep = 0; rep < 2; rep++) {
        int j = tid + rep * 512;
        float s = 0.0f;
        #pragma unroll
        for (int i = 0; i < R; i++)
            s += tile[i * N + j] * a_sm[i];
        g_part[(size_t)blockIdx.x * N + j] = s;
    }
}

// b_j = 1 / sum over the 64 row-tiles' partials
__global__ void sinkhorn_combine_kernel()
{
    int idx = blockIdx.x * blockDim.x + threadIdx.x;  // 0 .. BATCH*N-1
    int m = idx >> 10;
    int j = idx & (N - 1);
    const float* p = g_part + (size_t)m * TILES_PER_MAT * N + j;
    float s = 0.0f;
    #pragma unroll
    for (int t = 0; t < TILES_PER_MAT; t++)
        s += p[t * N];
    g_b[idx] = 1.0f / s;
}

// out = exp(A) * a_i * b_j   (vectorized float4)
__global__ void sinkhorn_final_kernel(const float* __restrict__ A,
                                      float* __restrict__ out)
{
    unsigned gid = blockIdx.x * blockDim.x + threadIdx.x; // 0 .. 16M-1 float4s
    int j4  = gid & 255;
    int row = (gid >> 8) & 1023;
    int m   = gid >> 18;

    float  a  = g_a[m * N + row];
    float4 bb = reinterpret_cast<const float4*>(g_b)[m * 256 + j4];
    float4 v  = reinterpret_cast<const float4*>(A)[gid];

    float4 o;
    o.x = __expf(v.x) * a * bb.x;
    o.y = __expf(v.y) * a * bb.y;
    o.z = __expf(v.z) * a * bb.z;
    o.w = __expf(v.w) * a * bb.w;
    reinterpret_cast<float4*>(out)[gid] = o;
}

extern "C" void kernel_launch(void* const* d_in, const int* in_sizes, int n_in,
                              void* d_out, int out_size)
{
    (void)in_sizes; (void)n_in; (void)out_size;
    const float* A   = (const float*)d_in[0];
    float*       out = (float*)d_out;

    // Opt in to 64 KB dynamic SMEM (idempotent; not a stream op, capture-safe)
    cudaFuncSetAttribute(sinkhorn_fused_kernel,
                         cudaFuncAttributeMaxDynamicSharedMemorySize,
                         R * N * (int)sizeof(float));

    const size_t smem = (size_t)R * N * sizeof(float);  // 64 KB
    for (int it = 0; it < ITERS; it++) {
        sinkhorn_fused_kernel<<<NTILES, THREADS, smem>>>(A, it == 0 ? 1 : 0);
        sinkhorn_combine_kernel<<<(BATCH * N) / 256, 256>>>();
    }
    // 64M elems / 4 per thread / 256 threads = 65536 blocks
    sinkhorn_final_kernel<<<65536, 256>>>(A, out);
}

// round 11
// speedup vs baseline: 1.1588x; 1.1588x over previous
#include <cuda_runtime.h>

// Sinkhorn-Knopp, 5 iterations, linear-domain scaling vectors, PERSISTENT
// L2-resident formulation.
//
//   a_i = 1 / sum_j exp(A_ij) * b_j   (b init 1)
//   b_j = 1 / sum_i exp(A_ij) * a_i   (uses fresh a)
//   out = exp(A_ij) * a_i * b_j
//
// 16 groups x 8 CTAs. Each group processes 4 matrices sequentially; each CTA
// owns a fixed 128-row (512 KB) slice and re-reads only that slice 6 times,
// so sweeps 2..6 hit L2 (instantaneous working set = 16 matrices = 64 MB).
// Cross-CTA column sums go through gmem partials + per-group atomic barrier
// (ping-pong buffers by phase parity; reads via __ldcg for coherence).
// 136 KB SMEM/CTA forces 1 CTA/SM -> all 128 CTAs co-resident (<=148 SMs),
// so the intra-group spin barrier cannot deadlock.

#define BATCH 64
#define N 1024
#define GROUPS 16
#define CPG 8                       // CTAs per group
#define MPG 4                       // matrices per group (64/16)
#define ROWS_PER_CTA 128            // N / CPG
#define CHUNK 32                    // rows staged in SMEM at a time
#define NCHUNKS (ROWS_PER_CTA / CHUNK)
#define THREADS 1024
#define ITERS 5
#define PHASES (MPG * ITERS)        // 20 barrier phases per group

// Scratch (allocation-free: __device__ globals)
__device__ float g_part[GROUPS][2][CPG][N];   // 1 MB ping-pong partials
__device__ int   g_bar[GROUPS][PHASES];       // one-shot barrier slots

__global__ __launch_bounds__(THREADS, 1)
void sinkhorn_persistent(const float* __restrict__ A, float* __restrict__ out)
{
    __shared__ float bs[N];                  // current column scales b
    __shared__ float colacc[N];              // this CTA's column partials
    __shared__ float a_sm[ROWS_PER_CTA];     // row scales a for owned rows
    extern __shared__ float tile[];          // CHUNK * N floats = 128 KB

    const int tid = threadIdx.x;
    const int g   = blockIdx.x / CPG;        // group id
    const int c   = blockIdx.x % CPG;        // rank within group
    const int w   = tid >> 5;                // warp 0..31
    const int l   = tid & 31;

    for (int k = 0; k < MPG; k++) {
        const int m = g * MPG + k;
        const float* Am = A + (size_t)m * N * N + (size_t)c * ROWS_PER_CTA * N;

        bs[tid] = 1.0f;                      // b starts at 1 (ordered by the
                                             // syncthreads after colacc zero)

        for (int it = 0; it < ITERS; it++) {
            colacc[tid] = 0.0f;
            __syncthreads();

            for (int ch = 0; ch < NCHUNKS; ch++) {
                // ---- Phase A: warp w owns row ch*32+w. Compute
                //      a = 1 / sum_j exp(A_ij)*b_j, stage exp in SMEM. ----
                const int row = ch * CHUNK + w;
                const float4* A4 =
                    reinterpret_cast<const float4*>(Am + (size_t)row * N);
                float4*       t4 = reinterpret_cast<float4*>(tile + w * N);
                const float4* b4 = reinterpret_cast<const float4*>(bs);

                float acc = 0.0f;
                #pragma unroll
                for (int q = 0; q < 8; q++) {
                    int c4 = q * 32 + l;
                    float4 v = A4[c4];
                    float4 e;
                    e.x = __expf(v.x); e.y = __expf(v.y);
                    e.z = __expf(v.z); e.w = __expf(v.w);
                    t4[c4] = e;
                    float4 bb = b4[c4];
                    acc += e.x * bb.x + e.y * bb.y + e.z * bb.z + e.w * bb.w;
                }
                #pragma unroll
                for (int o = 16; o; o >>= 1)
                    acc += __shfl_xor_sync(0xffffffffu, acc, o);
                if (l == 0) a_sm[row] = 1.0f / acc;
                __syncthreads();

                // ---- Phase B: column partials over this chunk's 32 rows ----
                float s = 0.0f;
                #pragma unroll
                for (int i = 0; i < CHUNK; i++)
                    s += tile[i * N + tid] * a_sm[ch * CHUNK + i];
                colacc[tid] += s;
                __syncthreads();             // tile reused by next chunk
            }

            // ---- Publish partials, group barrier, update b ----
            const int p   = k * ITERS + it;  // global phase index for group
            const int buf = p & 1;
            g_part[g][buf][c][tid] = colacc[tid];
            __threadfence();                 // release: partials -> device
            __syncthreads();                 // all threads' stores+fences done
            if (tid == 0) {
                atomicAdd(&g_bar[g][p], 1);
                while (atomicAdd(&g_bar[g][p], 0) < CPG) {}
            }
            __syncthreads();

            float s2 = 0.0f;
            #pragma unroll
            for (int cc = 0; cc < CPG; cc++)
                s2 += __ldcg(&g_part[g][buf][cc][tid]);  // L1-bypass: fresh
            bs[tid] = 1.0f / s2;
            // next iteration's colacc-zero __syncthreads orders bs
        }
        __syncthreads();                     // bs, a_sm final & visible

        // ---- Final pass: out = exp(A) * a_i * b_j over owned rows ----
        const float4* A4 = reinterpret_cast<const float4*>(Am);
        float4* O4 = reinterpret_cast<float4*>(
            out + (size_t)m * N * N + (size_t)c * ROWS_PER_CTA * N);
        const float4* b4 = reinterpret_cast<const float4*>(bs);
        #pragma unroll 4
        for (int idx = tid; idx < ROWS_PER_CTA * (N / 4); idx += THREADS) {
            int row = idx >> 8;
            int c4  = idx & 255;
            float  a  = a_sm[row];
            float4 v  = A4[idx];
            float4 bb = b4[c4];
            float4 o;
            o.x = __expf(v.x) * a * bb.x;
            o.y = __expf(v.y) * a * bb.y;
            o.z = __expf(v.z) * a * bb.z;
            o.w = __expf(v.w) * a * bb.w;
            O4[idx] = o;
        }
        __syncthreads();                     // bs/a_sm reads done before reuse
    }
}

extern "C" void kernel_launch(void* const* d_in, const int* in_sizes, int n_in,
                              void* d_out, int out_size)
{
    (void)in_sizes; (void)n_in; (void)out_size;
    const float* A   = (const float*)d_in[0];
    float*       out = (float*)d_out;

    // 128 KB dynamic SMEM (forces 1 CTA/SM together with 8.5 KB static)
    cudaFuncSetAttribute(sinkhorn_persistent,
                         cudaFuncAttributeMaxDynamicSharedMemorySize,
                         CHUNK * N * (int)sizeof(float));

    // Barrier slots must be zero on every launch (graph replays the kernel).
    void* bar_ptr = nullptr;
    cudaGetSymbolAddress(&bar_ptr, g_bar);
    cudaMemsetAsync(bar_ptr, 0, sizeof(int) * GROUPS * PHASES);

    sinkhorn_persistent<<<GROUPS * CPG, THREADS,
                          CHUNK * N * sizeof(float)>>>(A, out);
}